// round 15
// baseline (speedup 1.0000x reference)
#include <cuda_runtime.h>
#include <cuda_fp16.h>
#include <stdint.h>
#include <math.h>

#define B_    64
#define T_    12
#define N_    800
#define CIN_  2
#define H_    64
#define HOR_  12
#define TC_H  2
#define KAPPA_ 0.05f
#define NB    (N_*B_)
#define CF0   208
#define CF1   384
#define MPAD  1664

// ---------------- device scratch ----------------
__device__ float g_A2[1600*800];
__device__ __align__(16) __half g_A2h[MPAD*800];   // single fp16 [G^T; G2]
__device__ float g_EMBX[B_*T_*N_*TC_H];
__device__ float g_EMBY[B_*HOR_*N_*TC_H];
__device__ float g_H0[NB*H_];
__device__ float g_H1[NB*H_];
__device__ float g_UR[NB*128];
__device__ float g_GO[NB*CIN_];
__device__ float g_Q [B_*8];
__device__ float g_ATTM[B_*N_*8];
__device__ __align__(16) __half g_F [NB*384];      // features: single fp16
__device__ __align__(16) __half g_FC[NB*384];
__device__ __align__(16) __half g_WGh[4][384*128]; // weights: fp16 split-2
__device__ __align__(16) __half g_WGl[4][384*128];
__device__ __align__(16) __half g_WCh[4][384*64];
__device__ __align__(16) __half g_WCl[4][384*64];

// ---------------- helpers ----------------
__device__ __forceinline__ unsigned su(void* p) {
    return (unsigned)__cvta_generic_to_shared(p);
}
__device__ __forceinline__ void cp16(void* dst, const void* src) {
    asm volatile("cp.async.ca.shared.global [%0],[%1],16;" :: "r"(su(dst)), "l"(src));
}
__device__ __forceinline__ void cp8(void* dst, const void* src) {
    asm volatile("cp.async.ca.shared.global [%0],[%1],8;" :: "r"(su(dst)), "l"(src));
}
__device__ __forceinline__ void cp_commit() {
    asm volatile("cp.async.commit_group;");
}
__device__ __forceinline__ void ldsm_x4(unsigned* r, unsigned addr) {
    asm volatile("ldmatrix.sync.aligned.m8n8.x4.shared.b16 {%0,%1,%2,%3},[%4];"
        : "=r"(r[0]),"=r"(r[1]),"=r"(r[2]),"=r"(r[3]) : "r"(addr));
}
__device__ __forceinline__ void ldsm_x2t(unsigned* r, unsigned addr) {
    asm volatile("ldmatrix.sync.aligned.m8n8.x2.trans.shared.b16 {%0,%1},[%2];"
        : "=r"(r[0]),"=r"(r[1]) : "r"(addr));
}
__device__ __forceinline__ void mma_f16(float* c, const unsigned* a, const unsigned* b) {
    asm volatile("mma.sync.aligned.m16n8k16.row.col.f32.f16.f16.f32 "
        "{%0,%1,%2,%3},{%4,%5,%6,%7},{%8,%9},{%0,%1,%2,%3};"
        : "+f"(c[0]),"+f"(c[1]),"+f"(c[2]),"+f"(c[3])
        : "r"(a[0]),"r"(a[1]),"r"(a[2]),"r"(a[3]),"r"(b[0]),"r"(b[1]));
}
__device__ __forceinline__ void hsplit(float v, __half* ph, __half* pl) {
    __half h = __float2half_rn(v);
    *ph = h;
    *pl = __float2half_rn(v - __half2float(h));
}

// ---------------- setup kernels ----------------
__global__ void transpose_kernel(const float* __restrict__ G) {
    __shared__ float t[32][33];
    int x = blockIdx.x*32 + threadIdx.x, y = blockIdx.y*32 + threadIdx.y;
    t[threadIdx.y][threadIdx.x] = G[y*N_ + x];
    __syncthreads();
    int x2 = blockIdx.y*32 + threadIdx.x, y2 = blockIdx.x*32 + threadIdx.y;
    g_A2[y2*N_ + x2] = t[threadIdx.x][threadIdx.y];
}

__global__ void __launch_bounds__(256) g2_kernel() {
    __shared__ float As[8][128], Bs[8][128];
    int tid = threadIdx.x;
    int i0 = blockIdx.y*128, j0 = blockIdx.x*128;
    int ty = tid>>4, tx = tid&15, rl = ty*4, cl = tx*4;
    int ar = tid>>1, ac = (tid&1)*4;
    int bk = tid>>5, bj = (tid&31)*4;
    float acc[8][8];
    #pragma unroll
    for (int i=0;i<8;i++) {
        #pragma unroll
        for (int j=0;j<8;j++) acc[i][j]=0.f;
    }
    for (int k0=0;k0<N_;k0+=8) {
        float4 av = make_float4(0,0,0,0);
        if (i0+ar < N_) av = *(const float4*)&g_A2[(long)(i0+ar)*N_ + k0+ac];
        As[ac+0][ar]=av.x; As[ac+1][ar]=av.y; As[ac+2][ar]=av.z; As[ac+3][ar]=av.w;
        float4 bv = make_float4(0,0,0,0);
        if (j0+bj < N_) bv = *(const float4*)&g_A2[(long)(k0+bk)*N_ + j0+bj];
        *(float4*)&Bs[bk][bj] = bv;
        __syncthreads();
        #pragma unroll
        for (int kk=0;kk<8;kk++) {
            float a[8], b[8];
            *(float4*)a     = *(const float4*)&As[kk][rl];
            *(float4*)(a+4) = *(const float4*)&As[kk][rl+64];
            *(float4*)b     = *(const float4*)&Bs[kk][cl];
            *(float4*)(b+4) = *(const float4*)&Bs[kk][cl+64];
            #pragma unroll
            for (int i=0;i<8;i++) {
                #pragma unroll
                for (int j=0;j<8;j++) acc[i][j] += a[i]*b[j];
            }
        }
        __syncthreads();
    }
    #pragma unroll
    for (int i=0;i<8;i++) {
        int r = i0 + (i<4 ? rl+i : 64+rl+i-4);
        if (r >= N_) continue;
        #pragma unroll
        for (int j=0;j<8;j++) {
            int c = j0 + (j<4 ? cl+j : 64+cl+j-4);
            if (c >= N_) continue;
            g_A2[(long)(N_+r)*N_ + c] = 2.f*acc[i][j] - (r==c ? 1.f : 0.f);
        }
    }
}

__global__ void split_a2() {
    int i = blockIdx.x*256 + threadIdx.x;
    if (i >= MPAD*800) return;
    float v = (i < 1600*800) ? g_A2[i] : 0.f;
    g_A2h[i] = __float2half_rn(v);
}

__global__ void fold_split(const float* __restrict__ W, int isGate, int widx,
                           int P, int O, int KT) {
    int idx = blockIdx.x*256 + threadIdx.x;
    if (idx >= KT*O) return;
    int row = idx / O, o = idx % O;
    float v = 0.f;
    if (row < 3*P) {
        int k = row / P, p = row % P;
        if (k == 0) v = W[idx] + KAPPA_*(W[(P+p)*O + o] + W[(2*P+p)*O + o]);
        else        v = (1.f - KAPPA_)*W[idx];
    }
    if (isGate) hsplit(v, &g_WGh[widx][idx], &g_WGl[widx][idx]);
    else        hsplit(v, &g_WCh[widx][idx], &g_WCl[widx][idx]);
}

__global__ void mlp_kernel(const float* __restrict__ Tin,
                           const float* __restrict__ W1, const float* __restrict__ b1,
                           const float* __restrict__ W2, const float* __restrict__ b2,
                           int dsel) {
    float* out = dsel ? g_EMBY : g_EMBX;
    int r = blockIdx.x, tid = threadIdx.x;
    __shared__ float tin[60];
    __shared__ float hid[10];
    if (tid < 60) tin[tid] = Tin[(long)r*60 + tid];
    __syncthreads();
    if (tid < 10) {
        float s = b1[tid];
        for (int i = 0; i < 60; i++) s += tin[i]*W1[i*10 + tid];
        hid[tid] = s;
    }
    __syncthreads();
    for (int o = tid; o < N_*TC_H; o += 256) {
        float s = b2[o];
        #pragma unroll
        for (int j = 0; j < 10; j++) s += hid[j]*W2[j*(N_*TC_H) + o];
        out[(long)r*(N_*TC_H) + o] = s;
    }
}

__global__ void zero_state() {
    int i = blockIdx.x*256 + threadIdx.x;
    if (i < NB*H_) { g_H0[i] = 0.f; g_H1[i] = 0.f; }
    if (i < NB*CIN_) g_GO[i] = 0.f;
    if (i < NB*4) {
        int row = i >> 2, c = 204 + (i & 3);
        long a = (long)row*CF0 + c;
        __half z = __float2half_rn(0.f);
        g_F[a] = z; g_FC[a] = z;
    }
}

// ---------------- feature builders ----------------
__global__ void build_xh0(const float* __restrict__ xs, int t, int isDec) {
    int idx = blockIdx.x*256 + threadIdx.x;
    if (idx >= NB*68) return;
    int c = idx % 68, row = idx / 68;
    int b = row % B_, n = row / B_;
    float v;
    if (isDec) {
        if (c < 2)      v = g_GO[row*2 + c];
        else if (c < 4) v = g_EMBY[(long)(b*HOR_ + t)*(N_*TC_H) + n*TC_H + (c-2)];
        else            v = g_H0[(long)row*64 + (c-4)];
    } else {
        if (c < 2)      v = xs[((long)(b*T_ + t)*N_ + n)*CIN_ + c];
        else if (c < 4) v = g_EMBX[(long)(b*T_ + t)*(N_*TC_H) + n*TC_H + (c-2)];
        else            v = g_H0[(long)row*64 + (c-4)];
    }
    g_F[(long)row*CF0 + c] = __float2half_rn(v);
}

__global__ void build_xh1() {
    int idx = blockIdx.x*256 + threadIdx.x;
    if (idx >= NB*128) return;
    int c = idx % 128, row = idx / 128;
    float v = (c < 64) ? g_H0[(long)row*64 + c] : g_H1[(long)row*64 + (c-64)];
    g_F[(long)row*CF1 + c] = __float2half_rn(v);
}

__global__ void build_fc0() {
    int idx = blockIdx.x*256 + threadIdx.x;
    if (idx >= NB*76) return;
    int j = idx % 76, row = idx / 76;
    long base = (long)row*CF0;
    if (j < 4) {
        g_FC[base+j] = g_F[base+j];
    } else if (j < 68) {
        int c = j - 4;
        float v = g_UR[(long)row*128 + 64 + c] * g_H0[(long)row*64 + c];
        g_FC[base+j] = __float2half_rn(v);
    } else if (j < 72) {
        int c = 68 + (j-68);
        g_FC[base+c] = g_F[base+c];
    } else {
        int c = 136 + (j-72);
        g_FC[base+c] = g_F[base+c];
    }
}

__global__ void build_rh1() {
    int idx = blockIdx.x*256 + threadIdx.x;
    if (idx >= NB*64) return;
    int c = idx & 63, row = idx >> 6;
    float v = g_UR[(long)row*128 + 64 + c] * g_H1[(long)row*64 + c];
    g_FC[(long)row*CF1 + 64 + c] = __float2half_rn(v);
}

// ---------------- tensor-core graph propagation (fp16, 128x256 tile) ----------
// stage (half elems): A 3072 | B 16*264=4224.  Warp grid 2(m)x4(n): tile 64x64.
#define P_STG 7296
__global__ void __launch_bounds__(256,1) prop_tc(int bufSel, int CF, int src_off,
                                                 int d1, int d2, int Psub) {
    extern __shared__ __half dynsm[];
    const __half* F = bufSel ? g_FC : g_F;
    __half* O = bufSel ? g_FC : g_F;
    int tid = threadIdx.x, lane = tid & 31, warp = tid >> 5;
    int m0 = blockIdx.y*128, n0 = blockIdx.x*256;
    int wm = warp >> 2, wn = warp & 3;     // 2 m-warps x 4 n-warps, 64x64 each
    long rowStride = (long)B_*CF;

    float acc[4][8][4];
    #pragma unroll
    for (int i=0;i<4;i++)
        #pragma unroll
        for (int j=0;j<8;j++)
            #pragma unroll
            for (int e=0;e<4;e++) acc[i][j][e]=0.f;

    int aRow = tid >> 1, aSeg = (tid & 1)*8;
    long aBase = (long)(m0 + aRow)*800 + aSeg;
    // B loader: 4 cp8 descriptors per thread (16 rows x 256 cols)
    int krv[4]; int smOff[4]; long bOffv[4];
    #pragma unroll
    for (int u=0; u<4; u++) {
        int i = tid + u*256;
        int kr = i >> 6, cc = (i & 63)*4;
        krv[u] = kr;
        smOff[u] = kr*264 + cc;
        int j = n0 + cc;
        int bo = j/Psub, co = j - bo*Psub;
        bOffv[u] = (long)bo*CF + src_off + co;
    }

    auto issue = [&](int k0, int s) {
        __half* bp = dynsm + s*P_STG;
        cp16(bp + aRow*24 + aSeg, g_A2h + aBase + k0);
        #pragma unroll
        for (int u=0; u<4; u++)
            cp8(bp + 3072 + smOff[u], F + (long)(k0+krv[u])*rowStride + bOffv[u]);
        cp_commit();
    };

    int grp = lane >> 3, rr = lane & 7;
    int arow = ((grp & 1) ? 8 : 0) + rr;
    int acol = (grp & 2) ? 8 : 0;
    int brow = lane & 15;

    issue(0, 0); issue(16, 1);
    for (int c = 0; c < 50; c++) {
        if (c < 49) asm volatile("cp.async.wait_group 1;");
        else        asm volatile("cp.async.wait_group 0;");
        __syncthreads();
        if (c + 2 < 50) issue((c+2)*16, (c+2)%3);
        __half* bp = dynsm + (c%3)*P_STG;
        unsigned fa[4][4], fb[8][2];
        #pragma unroll
        for (int mi=0; mi<4; mi++)
            ldsm_x4(fa[mi], su(bp + (wm*64 + mi*16 + arow)*24 + acol));
        #pragma unroll
        for (int ni=0; ni<8; ni++)
            ldsm_x2t(fb[ni], su(bp + 3072 + brow*264 + wn*64 + ni*8));
        #pragma unroll
        for (int mi=0; mi<4; mi++)
            #pragma unroll
            for (int ni=0; ni<8; ni++)
                mma_f16(acc[mi][ni], fa[mi], fb[ni]);
    }

    #pragma unroll
    for (int mi=0; mi<4; mi++)
        #pragma unroll
        for (int ni=0; ni<8; ni++) {
            int rb = m0 + wm*64 + mi*16 + (lane >> 2);
            int cb = n0 + wn*64 + ni*8 + 2*(lane & 3);
            int bo = cb / Psub, co = cb - bo*Psub;
            #pragma unroll
            for (int hh=0; hh<2; hh++) {
                int gr = rb + hh*8;
                if (gr >= 1600) continue;
                int gm  = (gr < 800) ? gr : gr - 800;
                int off = (gr < 800) ? d1 : d2;
                long a = (long)gm*rowStride + (long)bo*CF + off + co;
                *(__half2*)&O[a] = __halves2half2(
                    __float2half_rn(acc[mi][ni][2*hh]),
                    __float2half_rn(acc[mi][ni][2*hh+1]));
            }
        }
}

// ---------------- tensor-core projection (fp16 2-product) ---------------------
template<int NO, int MODE>
__global__ void __launch_bounds__(256) proj_tc(int srcMode, int CF, int KT, int wsel,
                                               const float* __restrict__ bias, int hsel) {
    extern __shared__ __half dynsm[];
    const __half* Wh = (MODE==0) ? g_WGh[wsel] : g_WCh[wsel];
    const __half* Wl = (MODE==0) ? g_WGl[wsel] : g_WCl[wsel];
    constexpr int WN = NO/32;
    constexpr int WM = 8/WN;
    constexpr int MT = (128/WM)/16;
    constexpr int BROW = NO + 8;
    constexpr int BSZ  = 16*BROW;
    constexpr int STG  = 3072 + 2*BSZ;
    int tid = threadIdx.x, lane = tid & 31, warp = tid >> 5;
    long row0 = (long)blockIdx.x*128;
    int wm = warp / WN, wn = warp % WN;
    float acc[MT][4][4];
    #pragma unroll
    for (int i=0;i<MT;i++)
        #pragma unroll
        for (int j=0;j<4;j++)
            #pragma unroll
            for (int e=0;e<4;e++) acc[i][j][e]=0.f;

    int aRow = tid >> 1, aSeg = (tid & 1)*8;
    long aBase = (row0 + aRow)*CF + aSeg;

    auto issue = [&](int k0, int s) {
        const __half* S;
        if (srcMode == 0)       S = g_F;
        else if (srcMode == 1)  S = g_FC;
        else if ((k0 >> 6) & 1) S = g_FC;
        else                    S = g_F;
        __half* bp = dynsm + s*STG;
        cp16(bp + aRow*24 + aSeg, S + aBase + k0);
        if (NO == 128) {
            int wr = tid >> 4, wc = (tid & 15)*8;
            long a = (long)(k0+wr)*NO + wc;
            cp16(bp + 3072 + wr*BROW + wc,       Wh + a);
            cp16(bp + 3072 + BSZ + wr*BROW + wc, Wl + a);
        } else if (tid < 128) {
            int wr = tid >> 3, wc = (tid & 7)*8;
            long a = (long)(k0+wr)*NO + wc;
            cp16(bp + 3072 + wr*BROW + wc,       Wh + a);
            cp16(bp + 3072 + BSZ + wr*BROW + wc, Wl + a);
        }
        cp_commit();
    };

    int grp = lane >> 3, rr = lane & 7;
    int arow = ((grp & 1) ? 8 : 0) + rr;
    int acol = (grp & 2) ? 8 : 0;
    int brow = lane & 15;

    int NC = KT / 16;
    issue(0, 0); issue(16, 1);
    for (int c = 0; c < NC; c++) {
        if (c < NC-1) asm volatile("cp.async.wait_group 1;");
        else          asm volatile("cp.async.wait_group 0;");
        __syncthreads();
        if (c + 2 < NC) issue((c+2)*16, (c+2)%3);
        __half* bp = dynsm + (c%3)*STG;
        unsigned fa[MT][4], fwh[4][2], fwl[4][2];
        #pragma unroll
        for (int mi=0; mi<MT; mi++)
            ldsm_x4(fa[mi], su(bp + (wm*(MT*16) + mi*16 + arow)*24 + acol));
        #pragma unroll
        for (int ni=0; ni<4; ni++) {
            int cc = wn*32 + ni*8;
            ldsm_x2t(fwh[ni], su(bp + 3072 + brow*BROW + cc));
            ldsm_x2t(fwl[ni], su(bp + 3072 + BSZ + brow*BROW + cc));
        }
        #pragma unroll
        for (int mi=0; mi<MT; mi++)
            #pragma unroll
            for (int ni=0; ni<4; ni++) {
                mma_f16(acc[mi][ni], fa[mi], fwh[ni]);
                mma_f16(acc[mi][ni], fa[mi], fwl[ni]);
            }
    }

    float* Hb = hsel ? g_H1 : g_H0;
    #pragma unroll
    for (int mi=0; mi<MT; mi++)
        #pragma unroll
        for (int ni=0; ni<4; ni++) {
            long rb = row0 + wm*(MT*16) + mi*16 + (lane >> 2);
            int  cb = wn*32 + ni*8 + 2*(lane & 3);
            #pragma unroll
            for (int e=0; e<4; e++) {
                long row = rb + ((e >= 2) ? 8 : 0);
                int  c   = cb + (e & 1);
                float v = acc[mi][ni][e] + bias[c];
                if (MODE == 0) {
                    g_UR[row*128 + c] = 1.f/(1.f + expf(-v));
                } else {
                    float cv = tanhf(v);
                    float u  = g_UR[row*128 + c];
                    float h  = Hb[row*64 + c];
                    Hb[row*64 + c] = (1.f - u)*h + u*cv;
                }
            }
        }
}

// ---------------- decoder memory attention + output projection ----------------
__global__ void query_kernel(const float* __restrict__ Wa) {
    int b = blockIdx.x, tid = threadIdx.x;
    float p[8];
    #pragma unroll
    for (int d = 0; d < 8; d++) p[d] = 0.f;
    for (int idx = tid; idx < N_*H_; idx += 256) {
        int n = idx >> 6, j = idx & 63;
        float v = g_H1[(long)(n*B_ + b)*64 + j];
        const float* w = Wa + (long)idx*8;
        #pragma unroll
        for (int d = 0; d < 8; d++) p[d] += v*w[d];
    }
    #pragma unroll
    for (int d = 0; d < 8; d++)
        for (int off = 16; off > 0; off >>= 1) p[d] += __shfl_down_sync(0xffffffffu, p[d], off);
    __shared__ float sm[8][8];
    int w = tid >> 5, l = tid & 31;
    if (l == 0) { for (int d = 0; d < 8; d++) sm[w][d] = p[d]; }
    __syncthreads();
    if (tid < 8) {
        float s = 0.f;
        for (int ww = 0; ww < 8; ww++) s += sm[ww][tid];
        g_Q[b*8 + tid] = s;
    }
}

__global__ void attm_kernel(const float* __restrict__ mem, const float* __restrict__ fcw) {
    int b = blockIdx.x, tid = threadIdx.x;
    __shared__ float am[8];
    if (tid == 0) {
        float q[8];
        for (int d = 0; d < 8; d++) q[d] = g_Q[b*8 + d];
        float s[4]; float mx = -1e30f;
        for (int m = 0; m < 4; m++) {
            float a = 0.f;
            for (int d = 0; d < 8; d++) a += q[d]*mem[m*8 + d];
            s[m] = a; mx = fmaxf(mx, a);
        }
        float den = 0.f;
        for (int m = 0; m < 4; m++) { s[m] = expf(s[m]-mx); den += s[m]; }
        for (int d = 0; d < 8; d++) {
            float a = 0.f;
            for (int m = 0; m < 4; m++) a += (s[m]/den)*mem[m*8 + d];
            am[d] = a;
        }
    }
    __syncthreads();
    for (int i = tid; i < N_*8; i += 256) {
        float s = 0.f;
        #pragma unroll
        for (int d = 0; d < 8; d++) s += am[d]*fcw[(long)d*(N_*8) + i];
        g_ATTM[(long)b*(N_*8) + i] = s;
    }
}

__global__ void out_kernel(const float* __restrict__ pW, const float* __restrict__ pb,
                           float* __restrict__ outp, int s) {
    int row = blockIdx.x*256 + threadIdx.x;
    if (row >= NB) return;
    int b = row % B_, n = row / B_;
    float a0 = pb[0], a1 = pb[1];
    const float* h = g_H1 + (long)row*64;
    #pragma unroll
    for (int j = 0; j < 64; j++) { float v = h[j]; a0 += v*pW[j*2]; a1 += v*pW[j*2+1]; }
    const float* at = g_ATTM + (long)b*(N_*8) + n*8;
    #pragma unroll
    for (int d = 0; d < 8; d++) { float v = at[d]; a0 += v*pW[(64+d)*2]; a1 += v*pW[(64+d)*2+1]; }
    a0 = fmaxf(a0, 0.f); a1 = fmaxf(a1, 0.f);
    g_GO[row*2] = a0; g_GO[row*2+1] = a1;
    long o = ((long)(b*HOR_ + s)*N_ + n)*CIN_;
    outp[o] = a0; outp[o+1] = a1;
}

// ---------------- orchestration ----------------
extern "C" void kernel_launch(void* const* d_in, const int* in_sizes, int n_in,
                              void* d_out, int out_size) {
    (void)in_sizes; (void)n_in; (void)out_size;
    const float* x_seq = (const float*)d_in[0];
    const float* t_x   = (const float*)d_in[1];
    const float* t_y   = (const float*)d_in[2];
    const float* G     = (const float*)d_in[3];
    const float* eWg0  = (const float*)d_in[4];  const float* ebg0 = (const float*)d_in[5];
    const float* eWc0  = (const float*)d_in[6];  const float* ebc0 = (const float*)d_in[7];
    const float* eWg1  = (const float*)d_in[8];  const float* ebg1 = (const float*)d_in[9];
    const float* eWc1  = (const float*)d_in[10]; const float* ebc1 = (const float*)d_in[11];
    const float* dWg0  = (const float*)d_in[12]; const float* dbg0 = (const float*)d_in[13];
    const float* dWc0  = (const float*)d_in[14]; const float* dbc0 = (const float*)d_in[15];
    const float* dWg1  = (const float*)d_in[16]; const float* dbg1 = (const float*)d_in[17];
    const float* dWc1  = (const float*)d_in[18]; const float* dbc1 = (const float*)d_in[19];
    const float* mW1   = (const float*)d_in[20]; const float* mb1  = (const float*)d_in[21];
    const float* mW2   = (const float*)d_in[22]; const float* mb2  = (const float*)d_in[23];
    const float* mem   = (const float*)d_in[24];
    const float* Wa    = (const float*)d_in[25];
    const float* fcw   = (const float*)d_in[26];
    const float* projW = (const float*)d_in[27];
    const float* projb = (const float*)d_in[28];
    float* outp = (float*)d_out;

    const int PROP_SMEM    = 3*P_STG*2;                  // 43776 B
    const int PROJ128_SMEM = 3*(3072 + 2*16*136)*2;      // 44544 B
    const int PROJ64_SMEM  = 3*(3072 + 2*16*72)*2;       // 32256 B
    cudaFuncSetAttribute(prop_tc, cudaFuncAttributeMaxDynamicSharedMemorySize, PROP_SMEM);
    cudaFuncSetAttribute(proj_tc<128,0>, cudaFuncAttributeMaxDynamicSharedMemorySize, PROJ128_SMEM);
    cudaFuncSetAttribute(proj_tc<64,1>, cudaFuncAttributeMaxDynamicSharedMemorySize, PROJ64_SMEM);

    transpose_kernel<<<dim3(25,25), dim3(32,32)>>>(G);
    g2_kernel<<<dim3(7,7), 256>>>();
    split_a2<<<(MPAD*800+255)/256, 256>>>();

    auto fold = [](const float* W, int isGate, int widx, int P, int O) {
        int KT = ((3*P + 15)/16)*16;
        fold_split<<<(KT*O+255)/256, 256>>>(W, isGate, widx, P, O, KT);
    };
    fold(eWg0,1,0,68,128);  fold(eWc0,0,0,68,64);
    fold(eWg1,1,1,128,128); fold(eWc1,0,1,128,64);
    fold(dWg0,1,2,68,128);  fold(dWc0,0,2,68,64);
    fold(dWg1,1,3,128,128); fold(dWc1,0,3,128,64);

    mlp_kernel<<<B_*T_,   256>>>(t_x, mW1, mb1, mW2, mb2, 0);
    mlp_kernel<<<B_*HOR_, 256>>>(t_y, mW1, mb1, mW2, mb2, 1);
    zero_state<<<(NB*H_+255)/256, 256>>>();

    auto cell0 = [&](int wsel, const float* bg, const float* bc) {
        prop_tc<<<dim3(17,13), 256, PROP_SMEM>>>(0, CF0, 0, 68, 136, 68);   // 4352 cols
        proj_tc<128,0><<<NB/128, 256, PROJ128_SMEM>>>(0, CF0, 208, wsel, bg, 0);
        build_fc0<<<(NB*76+255)/256, 256>>>();
        prop_tc<<<dim3(16,13), 256, PROP_SMEM>>>(1, CF0, 4, 72, 140, 64);   // 4096 cols
        proj_tc<64,1><<<NB/128, 256, PROJ64_SMEM>>>(1, CF0, 208, wsel, bc, 0);
    };
    auto cell1 = [&](int wsel, const float* bg, const float* bc) {
        prop_tc<<<dim3(32,13), 256, PROP_SMEM>>>(0, CF1, 0, 128, 256, 128); // 8192 cols
        proj_tc<128,0><<<NB/128, 256, PROJ128_SMEM>>>(0, CF1, 384, wsel, bg, 1);
        build_rh1<<<(NB*64+255)/256, 256>>>();
        prop_tc<<<dim3(16,13), 256, PROP_SMEM>>>(1, CF1, 64, 192, 320, 64); // 4096 cols
        proj_tc<64,1><<<NB/128, 256, PROJ64_SMEM>>>(2, CF1, 384, wsel, bc, 1);
    };

    // encoder
    for (int t = 0; t < T_; t++) {
        build_xh0<<<(NB*68+255)/256, 256>>>(x_seq, t, 0);
        cell0(0, ebg0, ebc0);
        build_xh1<<<(NB*128+255)/256, 256>>>();
        cell1(1, ebg1, ebc1);
    }
    // decoder
    for (int s = 0; s < HOR_; s++) {
        build_xh0<<<(NB*68+255)/256, 256>>>(x_seq, s, 1);
        cell0(2, dbg0, dbc0);
        build_xh1<<<(NB*128+255)/256, 256>>>();
        cell1(3, dbg1, dbc1);
        query_kernel<<<B_, 256>>>(Wa);
        attm_kernel<<<B_, 256>>>(mem, fcw);
        out_kernel<<<NB/256, 256>>>(projW, projb, outp, s);
    }
}

// round 16
// speedup vs baseline: 1.0853x; 1.0853x over previous
#include <cuda_runtime.h>
#include <cuda_fp16.h>
#include <stdint.h>
#include <math.h>

#define B_    64
#define T_    12
#define N_    800
#define CIN_  2
#define H_    64
#define HOR_  12
#define TC_H  2
#define KAPPA_ 0.05f
#define NB    (N_*B_)
#define CF0   208
#define CF1   384
#define MPAD  1664

// ---------------- device scratch ----------------
__device__ float g_A2[1600*800];
__device__ __align__(16) __half g_A2h[MPAD*800];   // single fp16 [G^T; G2]
__device__ float g_EMBX[B_*T_*N_*TC_H];
__device__ float g_EMBY[B_*HOR_*N_*TC_H];
__device__ float g_H0[NB*H_];
__device__ float g_H1[NB*H_];
__device__ float g_UR[NB*128];
__device__ float g_GO[NB*CIN_];
__device__ float g_Q [B_*8];
__device__ float g_ATTM[B_*N_*8];
__device__ __align__(16) __half g_F [NB*384];      // features: single fp16
__device__ __align__(16) __half g_FC[NB*384];
__device__ __align__(16) __half g_WG[4][384*128];  // weights: single fp16
__device__ __align__(16) __half g_WC[4][384*64];

// ---------------- helpers ----------------
__device__ __forceinline__ unsigned su(void* p) {
    return (unsigned)__cvta_generic_to_shared(p);
}
__device__ __forceinline__ void cp16(void* dst, const void* src) {
    asm volatile("cp.async.ca.shared.global [%0],[%1],16;" :: "r"(su(dst)), "l"(src));
}
__device__ __forceinline__ void cp8(void* dst, const void* src) {
    asm volatile("cp.async.ca.shared.global [%0],[%1],8;" :: "r"(su(dst)), "l"(src));
}
__device__ __forceinline__ void cp_commit() {
    asm volatile("cp.async.commit_group;");
}
__device__ __forceinline__ void ldsm_x4(unsigned* r, unsigned addr) {
    asm volatile("ldmatrix.sync.aligned.m8n8.x4.shared.b16 {%0,%1,%2,%3},[%4];"
        : "=r"(r[0]),"=r"(r[1]),"=r"(r[2]),"=r"(r[3]) : "r"(addr));
}
__device__ __forceinline__ void ldsm_x2t(unsigned* r, unsigned addr) {
    asm volatile("ldmatrix.sync.aligned.m8n8.x2.trans.shared.b16 {%0,%1},[%2];"
        : "=r"(r[0]),"=r"(r[1]) : "r"(addr));
}
__device__ __forceinline__ void mma_f16(float* c, const unsigned* a, const unsigned* b) {
    asm volatile("mma.sync.aligned.m16n8k16.row.col.f32.f16.f16.f32 "
        "{%0,%1,%2,%3},{%4,%5,%6,%7},{%8,%9},{%0,%1,%2,%3};"
        : "+f"(c[0]),"+f"(c[1]),"+f"(c[2]),"+f"(c[3])
        : "r"(a[0]),"r"(a[1]),"r"(a[2]),"r"(a[3]),"r"(b[0]),"r"(b[1]));
}

// ---------------- setup kernels ----------------
__global__ void transpose_kernel(const float* __restrict__ G) {
    __shared__ float t[32][33];
    int x = blockIdx.x*32 + threadIdx.x, y = blockIdx.y*32 + threadIdx.y;
    t[threadIdx.y][threadIdx.x] = G[y*N_ + x];
    __syncthreads();
    int x2 = blockIdx.y*32 + threadIdx.x, y2 = blockIdx.x*32 + threadIdx.y;
    g_A2[y2*N_ + x2] = t[threadIdx.x][threadIdx.y];
}

__global__ void __launch_bounds__(256) g2_kernel() {
    __shared__ float As[8][128], Bs[8][128];
    int tid = threadIdx.x;
    int i0 = blockIdx.y*128, j0 = blockIdx.x*128;
    int ty = tid>>4, tx = tid&15, rl = ty*4, cl = tx*4;
    int ar = tid>>1, ac = (tid&1)*4;
    int bk = tid>>5, bj = (tid&31)*4;
    float acc[8][8];
    #pragma unroll
    for (int i=0;i<8;i++) {
        #pragma unroll
        for (int j=0;j<8;j++) acc[i][j]=0.f;
    }
    for (int k0=0;k0<N_;k0+=8) {
        float4 av = make_float4(0,0,0,0);
        if (i0+ar < N_) av = *(const float4*)&g_A2[(long)(i0+ar)*N_ + k0+ac];
        As[ac+0][ar]=av.x; As[ac+1][ar]=av.y; As[ac+2][ar]=av.z; As[ac+3][ar]=av.w;
        float4 bv = make_float4(0,0,0,0);
        if (j0+bj < N_) bv = *(const float4*)&g_A2[(long)(k0+bk)*N_ + j0+bj];
        *(float4*)&Bs[bk][bj] = bv;
        __syncthreads();
        #pragma unroll
        for (int kk=0;kk<8;kk++) {
            float a[8], b[8];
            *(float4*)a     = *(const float4*)&As[kk][rl];
            *(float4*)(a+4) = *(const float4*)&As[kk][rl+64];
            *(float4*)b     = *(const float4*)&Bs[kk][cl];
            *(float4*)(b+4) = *(const float4*)&Bs[kk][cl+64];
            #pragma unroll
            for (int i=0;i<8;i++) {
                #pragma unroll
                for (int j=0;j<8;j++) acc[i][j] += a[i]*b[j];
            }
        }
        __syncthreads();
    }
    #pragma unroll
    for (int i=0;i<8;i++) {
        int r = i0 + (i<4 ? rl+i : 64+rl+i-4);
        if (r >= N_) continue;
        #pragma unroll
        for (int j=0;j<8;j++) {
            int c = j0 + (j<4 ? cl+j : 64+cl+j-4);
            if (c >= N_) continue;
            g_A2[(long)(N_+r)*N_ + c] = 2.f*acc[i][j] - (r==c ? 1.f : 0.f);
        }
    }
}

__global__ void split_a2() {
    int i = blockIdx.x*256 + threadIdx.x;
    if (i >= MPAD*800) return;
    float v = (i < 1600*800) ? g_A2[i] : 0.f;
    g_A2h[i] = __float2half_rn(v);
}

__global__ void fold_split(const float* __restrict__ W, int isGate, int widx,
                           int P, int O, int KT) {
    int idx = blockIdx.x*256 + threadIdx.x;
    if (idx >= KT*O) return;
    int row = idx / O, o = idx % O;
    float v = 0.f;
    if (row < 3*P) {
        int k = row / P, p = row % P;
        if (k == 0) v = W[idx] + KAPPA_*(W[(P+p)*O + o] + W[(2*P+p)*O + o]);
        else        v = (1.f - KAPPA_)*W[idx];
    }
    if (isGate) g_WG[widx][idx] = __float2half_rn(v);
    else        g_WC[widx][idx] = __float2half_rn(v);
}

__global__ void mlp_kernel(const float* __restrict__ Tin,
                           const float* __restrict__ W1, const float* __restrict__ b1,
                           const float* __restrict__ W2, const float* __restrict__ b2,
                           int dsel) {
    float* out = dsel ? g_EMBY : g_EMBX;
    int r = blockIdx.x, tid = threadIdx.x;
    __shared__ float tin[60];
    __shared__ float hid[10];
    if (tid < 60) tin[tid] = Tin[(long)r*60 + tid];
    __syncthreads();
    if (tid < 10) {
        float s = b1[tid];
        for (int i = 0; i < 60; i++) s += tin[i]*W1[i*10 + tid];
        hid[tid] = s;
    }
    __syncthreads();
    for (int o = tid; o < N_*TC_H; o += 256) {
        float s = b2[o];
        #pragma unroll
        for (int j = 0; j < 10; j++) s += hid[j]*W2[j*(N_*TC_H) + o];
        out[(long)r*(N_*TC_H) + o] = s;
    }
}

__global__ void zero_state() {
    int i = blockIdx.x*256 + threadIdx.x;
    if (i < NB*H_) { g_H0[i] = 0.f; g_H1[i] = 0.f; }
    if (i < NB*CIN_) g_GO[i] = 0.f;
    if (i < NB*4) {
        int row = i >> 2, c = 204 + (i & 3);
        long a = (long)row*CF0 + c;
        __half z = __float2half_rn(0.f);
        g_F[a] = z; g_FC[a] = z;
    }
}

// ---------------- feature builders ----------------
__global__ void build_xh0(const float* __restrict__ xs, int t, int isDec) {
    int idx = blockIdx.x*256 + threadIdx.x;
    if (idx >= NB*68) return;
    int c = idx % 68, row = idx / 68;
    int b = row % B_, n = row / B_;
    float v;
    if (isDec) {
        if (c < 2)      v = g_GO[row*2 + c];
        else if (c < 4) v = g_EMBY[(long)(b*HOR_ + t)*(N_*TC_H) + n*TC_H + (c-2)];
        else            v = g_H0[(long)row*64 + (c-4)];
    } else {
        if (c < 2)      v = xs[((long)(b*T_ + t)*N_ + n)*CIN_ + c];
        else if (c < 4) v = g_EMBX[(long)(b*T_ + t)*(N_*TC_H) + n*TC_H + (c-2)];
        else            v = g_H0[(long)row*64 + (c-4)];
    }
    g_F[(long)row*CF0 + c] = __float2half_rn(v);
}

__global__ void build_xh1() {
    int idx = blockIdx.x*256 + threadIdx.x;
    if (idx >= NB*128) return;
    int c = idx % 128, row = idx / 128;
    float v = (c < 64) ? g_H0[(long)row*64 + c] : g_H1[(long)row*64 + (c-64)];
    g_F[(long)row*CF1 + c] = __float2half_rn(v);
}

__global__ void build_fc0() {
    int idx = blockIdx.x*256 + threadIdx.x;
    if (idx >= NB*76) return;
    int j = idx % 76, row = idx / 76;
    long base = (long)row*CF0;
    if (j < 4) {
        g_FC[base+j] = g_F[base+j];
    } else if (j < 68) {
        int c = j - 4;
        float v = g_UR[(long)row*128 + 64 + c] * g_H0[(long)row*64 + c];
        g_FC[base+j] = __float2half_rn(v);
    } else if (j < 72) {
        int c = 68 + (j-68);
        g_FC[base+c] = g_F[base+c];
    } else {
        int c = 136 + (j-72);
        g_FC[base+c] = g_F[base+c];
    }
}

__global__ void build_rh1() {
    int idx = blockIdx.x*256 + threadIdx.x;
    if (idx >= NB*64) return;
    int c = idx & 63, row = idx >> 6;
    float v = g_UR[(long)row*128 + 64 + c] * g_H1[(long)row*64 + c];
    g_FC[(long)row*CF1 + 64 + c] = __float2half_rn(v);
}

// ---------------- tensor-core graph propagation (fp16, single A) --------------
// stage (half elems): A 3072 | B 2176.  Warp grid 2(m)x4(n): tile 64x32.
#define P_STG 5248
__global__ void __launch_bounds__(256) prop_tc(int bufSel, int CF, int src_off,
                                               int d1, int d2, int Psub) {
    extern __shared__ __half dynsm[];
    const __half* F = bufSel ? g_FC : g_F;
    __half* O = bufSel ? g_FC : g_F;
    int tid = threadIdx.x, lane = tid & 31, warp = tid >> 5;
    int m0 = blockIdx.y*128, n0 = blockIdx.x*128;
    int wm = warp >> 2, wn = warp & 3;
    long rowStride = (long)B_*CF;

    float acc[4][4][4];
    #pragma unroll
    for (int i=0;i<4;i++)
        #pragma unroll
        for (int j=0;j<4;j++)
            #pragma unroll
            for (int e=0;e<4;e++) acc[i][j][e]=0.f;

    int aRow = tid >> 1, aSeg = (tid & 1)*8;
    long aBase = (long)(m0 + aRow)*800 + aSeg;
    int kr0 = tid >> 5,        cc0 = (tid & 31)*4;
    int kr1 = (tid+256) >> 5,  cc1 = (tid & 31)*4;
    int j0g = n0 + cc0, j1g = n0 + cc1;
    int bo0 = j0g/Psub, co0 = j0g - bo0*Psub;
    int bo1 = j1g/Psub, co1 = j1g - bo1*Psub;
    long bOff0 = (long)bo0*CF + src_off + co0;
    long bOff1 = (long)bo1*CF + src_off + co1;

    auto issue = [&](int k0, int s) {
        __half* bp = dynsm + s*P_STG;
        cp16(bp + aRow*24 + aSeg, g_A2h + aBase + k0);
        cp8(bp + 3072 + kr0*136 + cc0, F + (long)(k0+kr0)*rowStride + bOff0);
        cp8(bp + 3072 + kr1*136 + cc1, F + (long)(k0+kr1)*rowStride + bOff1);
        cp_commit();
    };

    int grp = lane >> 3, rr = lane & 7;
    int arow = ((grp & 1) ? 8 : 0) + rr;
    int acol = (grp & 2) ? 8 : 0;
    int brow = lane & 15;

    issue(0, 0); issue(16, 1);
    for (int c = 0; c < 50; c++) {
        if (c < 49) asm volatile("cp.async.wait_group 1;");
        else        asm volatile("cp.async.wait_group 0;");
        __syncthreads();
        if (c + 2 < 50) issue((c+2)*16, (c+2)%3);
        __half* bp = dynsm + (c%3)*P_STG;
        unsigned fa[4][4], fb[4][2];
        #pragma unroll
        for (int mi=0; mi<4; mi++)
            ldsm_x4(fa[mi], su(bp + (wm*64 + mi*16 + arow)*24 + acol));
        #pragma unroll
        for (int ni=0; ni<4; ni++)
            ldsm_x2t(fb[ni], su(bp + 3072 + brow*136 + wn*32 + ni*8));
        #pragma unroll
        for (int mi=0; mi<4; mi++)
            #pragma unroll
            for (int ni=0; ni<4; ni++)
                mma_f16(acc[mi][ni], fa[mi], fb[ni]);
    }

    #pragma unroll
    for (int mi=0; mi<4; mi++)
        #pragma unroll
        for (int ni=0; ni<4; ni++) {
            int rb = m0 + wm*64 + mi*16 + (lane >> 2);
            int cb = n0 + wn*32 + ni*8 + 2*(lane & 3);
            int bo = cb / Psub, co = cb - bo*Psub;
            #pragma unroll
            for (int hh=0; hh<2; hh++) {
                int gr = rb + hh*8;
                if (gr >= 1600) continue;
                int gm  = (gr < 800) ? gr : gr - 800;
                int off = (gr < 800) ? d1 : d2;
                long a = (long)gm*rowStride + (long)bo*CF + off + co;
                *(__half2*)&O[a] = __halves2half2(
                    __float2half_rn(acc[mi][ni][2*hh]),
                    __float2half_rn(acc[mi][ni][2*hh+1]));
            }
        }
}

// ---------------- tensor-core projection (fp16, single W) ---------------------
template<int NO, int MODE>
__global__ void __launch_bounds__(256) proj_tc(int srcMode, int CF, int KT, int wsel,
                                               const float* __restrict__ bias, int hsel) {
    extern __shared__ __half dynsm[];
    const __half* W = (MODE==0) ? g_WG[wsel] : g_WC[wsel];
    constexpr int WN = NO/32;
    constexpr int WM = 8/WN;
    constexpr int MT = (128/WM)/16;
    constexpr int BROW = NO + 8;
    constexpr int BSZ  = 16*BROW;
    constexpr int STG  = 3072 + BSZ;
    int tid = threadIdx.x, lane = tid & 31, warp = tid >> 5;
    long row0 = (long)blockIdx.x*128;
    int wm = warp / WN, wn = warp % WN;
    float acc[MT][4][4];
    #pragma unroll
    for (int i=0;i<MT;i++)
        #pragma unroll
        for (int j=0;j<4;j++)
            #pragma unroll
            for (int e=0;e<4;e++) acc[i][j][e]=0.f;

    int aRow = tid >> 1, aSeg = (tid & 1)*8;
    long aBase = (row0 + aRow)*CF + aSeg;

    auto issue = [&](int k0, int s) {
        const __half* S;
        if (srcMode == 0)       S = g_F;
        else if (srcMode == 1)  S = g_FC;
        else if ((k0 >> 6) & 1) S = g_FC;
        else                    S = g_F;
        __half* bp = dynsm + s*STG;
        cp16(bp + aRow*24 + aSeg, S + aBase + k0);
        if (NO == 128) {
            int wr = tid >> 4, wc = (tid & 15)*8;
            cp16(bp + 3072 + wr*BROW + wc, W + (long)(k0+wr)*NO + wc);
        } else if (tid < 128) {
            int wr = tid >> 3, wc = (tid & 7)*8;
            cp16(bp + 3072 + wr*BROW + wc, W + (long)(k0+wr)*NO + wc);
        }
        cp_commit();
    };

    int grp = lane >> 3, rr = lane & 7;
    int arow = ((grp & 1) ? 8 : 0) + rr;
    int acol = (grp & 2) ? 8 : 0;
    int brow = lane & 15;

    int NC = KT / 16;
    issue(0, 0); issue(16, 1);
    for (int c = 0; c < NC; c++) {
        if (c < NC-1) asm volatile("cp.async.wait_group 1;");
        else          asm volatile("cp.async.wait_group 0;");
        __syncthreads();
        if (c + 2 < NC) issue((c+2)*16, (c+2)%3);
        __half* bp = dynsm + (c%3)*STG;
        unsigned fa[MT][4], fw[4][2];
        #pragma unroll
        for (int mi=0; mi<MT; mi++)
            ldsm_x4(fa[mi], su(bp + (wm*(MT*16) + mi*16 + arow)*24 + acol));
        #pragma unroll
        for (int ni=0; ni<4; ni++)
            ldsm_x2t(fw[ni], su(bp + 3072 + brow*BROW + wn*32 + ni*8));
        #pragma unroll
        for (int mi=0; mi<MT; mi++)
            #pragma unroll
            for (int ni=0; ni<4; ni++)
                mma_f16(acc[mi][ni], fa[mi], fw[ni]);
    }

    float* Hb = hsel ? g_H1 : g_H0;
    #pragma unroll
    for (int mi=0; mi<MT; mi++)
        #pragma unroll
        for (int ni=0; ni<4; ni++) {
            long rb = row0 + wm*(MT*16) + mi*16 + (lane >> 2);
            int  cb = wn*32 + ni*8 + 2*(lane & 3);
            #pragma unroll
            for (int e=0; e<4; e++) {
                long row = rb + ((e >= 2) ? 8 : 0);
                int  c   = cb + (e & 1);
                float v = acc[mi][ni][e] + bias[c];
                if (MODE == 0) {
                    g_UR[row*128 + c] = 1.f/(1.f + expf(-v));
                } else {
                    float cv = tanhf(v);
                    float u  = g_UR[row*128 + c];
                    float h  = Hb[row*64 + c];
                    Hb[row*64 + c] = (1.f - u)*h + u*cv;
                }
            }
        }
}

// ---------------- decoder memory attention + output projection ----------------
__global__ void query_kernel(const float* __restrict__ Wa) {
    int b = blockIdx.x, tid = threadIdx.x;
    float p[8];
    #pragma unroll
    for (int d = 0; d < 8; d++) p[d] = 0.f;
    for (int idx = tid; idx < N_*H_; idx += 256) {
        int n = idx >> 6, j = idx & 63;
        float v = g_H1[(long)(n*B_ + b)*64 + j];
        const float* w = Wa + (long)idx*8;
        #pragma unroll
        for (int d = 0; d < 8; d++) p[d] += v*w[d];
    }
    #pragma unroll
    for (int d = 0; d < 8; d++)
        for (int off = 16; off > 0; off >>= 1) p[d] += __shfl_down_sync(0xffffffffu, p[d], off);
    __shared__ float sm[8][8];
    int w = tid >> 5, l = tid & 31;
    if (l == 0) { for (int d = 0; d < 8; d++) sm[w][d] = p[d]; }
    __syncthreads();
    if (tid < 8) {
        float s = 0.f;
        for (int ww = 0; ww < 8; ww++) s += sm[ww][tid];
        g_Q[b*8 + tid] = s;
    }
}

__global__ void attm_kernel(const float* __restrict__ mem, const float* __restrict__ fcw) {
    int b = blockIdx.x, tid = threadIdx.x;
    __shared__ float am[8];
    if (tid == 0) {
        float q[8];
        for (int d = 0; d < 8; d++) q[d] = g_Q[b*8 + d];
        float s[4]; float mx = -1e30f;
        for (int m = 0; m < 4; m++) {
            float a = 0.f;
            for (int d = 0; d < 8; d++) a += q[d]*mem[m*8 + d];
            s[m] = a; mx = fmaxf(mx, a);
        }
        float den = 0.f;
        for (int m = 0; m < 4; m++) { s[m] = expf(s[m]-mx); den += s[m]; }
        for (int d = 0; d < 8; d++) {
            float a = 0.f;
            for (int m = 0; m < 4; m++) a += (s[m]/den)*mem[m*8 + d];
            am[d] = a;
        }
    }
    __syncthreads();
    for (int i = tid; i < N_*8; i += 256) {
        float s = 0.f;
        #pragma unroll
        for (int d = 0; d < 8; d++) s += am[d]*fcw[(long)d*(N_*8) + i];
        g_ATTM[(long)b*(N_*8) + i] = s;
    }
}

__global__ void out_kernel(const float* __restrict__ pW, const float* __restrict__ pb,
                           float* __restrict__ outp, int s) {
    int row = blockIdx.x*256 + threadIdx.x;
    if (row >= NB) return;
    int b = row % B_, n = row / B_;
    float a0 = pb[0], a1 = pb[1];
    const float* h = g_H1 + (long)row*64;
    #pragma unroll
    for (int j = 0; j < 64; j++) { float v = h[j]; a0 += v*pW[j*2]; a1 += v*pW[j*2+1]; }
    const float* at = g_ATTM + (long)b*(N_*8) + n*8;
    #pragma unroll
    for (int d = 0; d < 8; d++) { float v = at[d]; a0 += v*pW[(64+d)*2]; a1 += v*pW[(64+d)*2+1]; }
    a0 = fmaxf(a0, 0.f); a1 = fmaxf(a1, 0.f);
    g_GO[row*2] = a0; g_GO[row*2+1] = a1;
    long o = ((long)(b*HOR_ + s)*N_ + n)*CIN_;
    outp[o] = a0; outp[o+1] = a1;
}

// ---------------- orchestration ----------------
extern "C" void kernel_launch(void* const* d_in, const int* in_sizes, int n_in,
                              void* d_out, int out_size) {
    (void)in_sizes; (void)n_in; (void)out_size;
    const float* x_seq = (const float*)d_in[0];
    const float* t_x   = (const float*)d_in[1];
    const float* t_y   = (const float*)d_in[2];
    const float* G     = (const float*)d_in[3];
    const float* eWg0  = (const float*)d_in[4];  const float* ebg0 = (const float*)d_in[5];
    const float* eWc0  = (const float*)d_in[6];  const float* ebc0 = (const float*)d_in[7];
    const float* eWg1  = (const float*)d_in[8];  const float* ebg1 = (const float*)d_in[9];
    const float* eWc1  = (const float*)d_in[10]; const float* ebc1 = (const float*)d_in[11];
    const float* dWg0  = (const float*)d_in[12]; const float* dbg0 = (const float*)d_in[13];
    const float* dWc0  = (const float*)d_in[14]; const float* dbc0 = (const float*)d_in[15];
    const float* dWg1  = (const float*)d_in[16]; const float* dbg1 = (const float*)d_in[17];
    const float* dWc1  = (const float*)d_in[18]; const float* dbc1 = (const float*)d_in[19];
    const float* mW1   = (const float*)d_in[20]; const float* mb1  = (const float*)d_in[21];
    const float* mW2   = (const float*)d_in[22]; const float* mb2  = (const float*)d_in[23];
    const float* mem   = (const float*)d_in[24];
    const float* Wa    = (const float*)d_in[25];
    const float* fcw   = (const float*)d_in[26];
    const float* projW = (const float*)d_in[27];
    const float* projb = (const float*)d_in[28];
    float* outp = (float*)d_out;

    const int PROP_SMEM    = 3*P_STG*2;              // 31488 B
    const int PROJ128_SMEM = 3*(3072 + 16*136)*2;    // 31488 B
    const int PROJ64_SMEM  = 3*(3072 + 16*72)*2;     // 25344 B
    cudaFuncSetAttribute(prop_tc, cudaFuncAttributeMaxDynamicSharedMemorySize, PROP_SMEM);
    cudaFuncSetAttribute(proj_tc<128,0>, cudaFuncAttributeMaxDynamicSharedMemorySize, PROJ128_SMEM);
    cudaFuncSetAttribute(proj_tc<64,1>, cudaFuncAttributeMaxDynamicSharedMemorySize, PROJ64_SMEM);

    transpose_kernel<<<dim3(25,25), dim3(32,32)>>>(G);
    g2_kernel<<<dim3(7,7), 256>>>();
    split_a2<<<(MPAD*800+255)/256, 256>>>();

    auto fold = [](const float* W, int isGate, int widx, int P, int O) {
        int KT = ((3*P + 15)/16)*16;
        fold_split<<<(KT*O+255)/256, 256>>>(W, isGate, widx, P, O, KT);
    };
    fold(eWg0,1,0,68,128);  fold(eWc0,0,0,68,64);
    fold(eWg1,1,1,128,128); fold(eWc1,0,1,128,64);
    fold(dWg0,1,2,68,128);  fold(dWc0,0,2,68,64);
    fold(dWg1,1,3,128,128); fold(dWc1,0,3,128,64);

    mlp_kernel<<<B_*T_,   256>>>(t_x, mW1, mb1, mW2, mb2, 0);
    mlp_kernel<<<B_*HOR_, 256>>>(t_y, mW1, mb1, mW2, mb2, 1);
    zero_state<<<(NB*H_+255)/256, 256>>>();

    auto cell0 = [&](int wsel, const float* bg, const float* bc) {
        prop_tc<<<dim3(34,13), 256, PROP_SMEM>>>(0, CF0, 0, 68, 136, 68);
        proj_tc<128,0><<<NB/128, 256, PROJ128_SMEM>>>(0, CF0, 208, wsel, bg, 0);
        build_fc0<<<(NB*76+255)/256, 256>>>();
        prop_tc<<<dim3(32,13), 256, PROP_SMEM>>>(1, CF0, 4, 72, 140, 64);
        proj_tc<64,1><<<NB/128, 256, PROJ64_SMEM>>>(1, CF0, 208, wsel, bc, 0);
    };
    auto cell1 = [&](int wsel, const float* bg, const float* bc) {
        prop_tc<<<dim3(64,13), 256, PROP_SMEM>>>(0, CF1, 0, 128, 256, 128);
        proj_tc<128,0><<<NB/128, 256, PROJ128_SMEM>>>(0, CF1, 384, wsel, bg, 1);
        build_rh1<<<(NB*64+255)/256, 256>>>();
        prop_tc<<<dim3(32,13), 256, PROP_SMEM>>>(1, CF1, 64, 192, 320, 64);
        proj_tc<64,1><<<NB/128, 256, PROJ64_SMEM>>>(2, CF1, 384, wsel, bc, 1);
    };

    // encoder
    for (int t = 0; t < T_; t++) {
        build_xh0<<<(NB*68+255)/256, 256>>>(x_seq, t, 0);
        cell0(0, ebg0, ebc0);
        build_xh1<<<(NB*128+255)/256, 256>>>();
        cell1(1, ebg1, ebc1);
    }
    // decoder
    for (int s = 0; s < HOR_; s++) {
        build_xh0<<<(NB*68+255)/256, 256>>>(x_seq, s, 1);
        cell0(2, dbg0, dbc0);
        build_xh1<<<(NB*128+255)/256, 256>>>();
        cell1(3, dbg1, dbc1);
        query_kernel<<<B_, 256>>>(Wa);
        attm_kernel<<<B_, 256>>>(mem, fcw);
        out_kernel<<<NB/256, 256>>>(projW, projb, outp, s);
    }
}